// round 14
// baseline (speedup 1.0000x reference)
#include <cuda_runtime.h>
#include <cuda_bf16.h>
#include <cstdint>

static constexpr int B_ = 8;
static constexpr int N_ = 2048;
static constexpr int F_ = 64;
static constexpr float ALPHA_ = 0.2f;
static constexpr int NCH = N_ / 64;      // 32 chunks, full j-range per block
static constexpr int TI = 64;            // rows per block

// -------- scratch (no cudaMalloc allowed) --------
__device__ float g_h[B_ * N_ * F_];
__device__ float g_s1[B_ * N_];
__device__ float g_s2[B_ * N_];
__device__ float g_c[B_];
__device__ float g_c2[B_];
__device__ float g_A [B_ * N_];
__device__ float g_Ap[B_ * N_];
__device__ float g_B [B_ * N_];
__device__ float g_Bp[B_ * N_];
__device__ __nv_bfloat16 g_hT_hi[B_ * F_ * N_];   // [b][f][n]
__device__ __nv_bfloat16 g_hT_lo[B_ * F_ * N_];
__device__ int g_nbad;
__device__ int g_bad[B_ * N_];

__device__ __forceinline__ uint32_t smem_u32(const void* p) {
    uint32_t a;
    asm("{ .reg .u64 t; cvta.to.shared.u64 t, %1; cvt.u32.u64 %0, t; }" : "=r"(a) : "l"(p));
    return a;
}

#define LDSM4(r, addr) \
    asm volatile("ldmatrix.sync.aligned.m8n8.x4.shared.b16 {%0,%1,%2,%3}, [%4];" \
        : "=r"((r)[0]), "=r"((r)[1]), "=r"((r)[2]), "=r"((r)[3]) : "r"(addr))

#define MMA_BF16(C, a, b0, b1) \
    asm volatile("mma.sync.aligned.m16n8k16.row.col.f32.bf16.bf16.f32 " \
        "{%0,%1,%2,%3}, {%4,%5,%6,%7}, {%8,%9}, {%0,%1,%2,%3};" \
        : "+f"((C)[0]), "+f"((C)[1]), "+f"((C)[2]), "+f"((C)[3]) \
        : "r"((a)[0]), "r"((a)[1]), "r"((a)[2]), "r"((a)[3]), "r"(b0), "r"(b1))

#define CP16(dst, src) \
    asm volatile("cp.async.cg.shared.global [%0], [%1], 16;" :: "r"(dst), "l"(src))
#define CP_COMMIT()  asm volatile("cp.async.commit_group;" ::: "memory")
#define CP_WAIT0()   asm volatile("cp.async.wait_group 0;" ::: "memory")
#define CP_WAIT1()   asm volatile("cp.async.wait_group 1;" ::: "memory")

// named block barriers (384 participants: 256 producer + 128 consumer threads)
#define BAR_SYNC(id)   asm volatile("bar.sync %0, 384;"   :: "r"(id) : "memory")
#define BAR_ARRIVE(id) asm volatile("bar.arrive %0, 384;" :: "r"(id) : "memory")

// ---------------------------------------------------------------------------
// K1: h = x@W ; s1,s2 ; transposed bf16 hi/lo copies of h
// ---------------------------------------------------------------------------
__global__ void __launch_bounds__(1024) prep_kernel(
    const float* __restrict__ x, const float* __restrict__ W, const float* __restrict__ a)
{
    __shared__ float W_s[F_ * F_];
    __shared__ float x_s[16][F_];
    __shared__ float h_sh[16][F_ + 1];
    __shared__ float red[16][2][2];

    int t = threadIdx.x, tx = t & 63, ty = t >> 6;
    int row0 = blockIdx.x * 16;
    int row = row0 + ty;

    #pragma unroll
    for (int k = 0; k < 4; ++k) W_s[t + k * 1024] = W[t + k * 1024];
    x_s[ty][tx] = x[(size_t)row * F_ + tx];
    __syncthreads();

    float h = 0.f;
    #pragma unroll
    for (int k = 0; k < F_; ++k) h = fmaf(x_s[ty][k], W_s[k * F_ + tx], h);
    g_h[(size_t)row * F_ + tx] = h;
    h_sh[ty][tx] = h;

    float v1 = h * a[tx];
    float v2 = h * a[F_ + tx];
    #pragma unroll
    for (int off = 16; off; off >>= 1) {
        v1 += __shfl_xor_sync(0xffffffffu, v1, off);
        v2 += __shfl_xor_sync(0xffffffffu, v2, off);
    }
    if ((tx & 31) == 0) { red[ty][tx >> 5][0] = v1; red[ty][tx >> 5][1] = v2; }
    __syncthreads();
    if (tx == 0) {
        g_s1[row] = red[ty][0][0] + red[ty][1][0];
        g_s2[row] = red[ty][0][1] + red[ty][1][1];
    }

    int f = t >> 4, rr = t & 15;
    float v = h_sh[rr][f];
    __nv_bfloat16 hi = __float2bfloat16(v);
    float lov = v - __bfloat162float(hi);
    int b = row0 >> 11;
    size_t o = ((size_t)(b * F_ + f)) * N_ + (row0 & (N_ - 1)) + rr;
    g_hT_hi[o] = hi;
    g_hT_lo[o] = __float2bfloat16(lov);
}

// ---------------------------------------------------------------------------
// K2: per-batch c (max of warp maxes) / c2 (min of warp maxes); reset counter
// ---------------------------------------------------------------------------
__global__ void __launch_bounds__(256) cmax_kernel() {
    __shared__ float red[8];
    int b = blockIdx.x, t = threadIdx.x, w = t >> 5, lane = t & 31;
    if (b == 0 && t == 0) g_nbad = 0;

    float m = -3.4e38f;
    for (int i = t; i < N_; i += 256) m = fmaxf(m, g_s2[b * N_ + i]);
    #pragma unroll
    for (int off = 16; off; off >>= 1) m = fmaxf(m, __shfl_xor_sync(0xffffffffu, m, off));
    if (lane == 0) red[w] = m;
    __syncthreads();
    if (t == 0) {
        float c = -3.4e38f, c2 = 3.4e38f;
        #pragma unroll
        for (int q = 0; q < 8; ++q) { c = fmaxf(c, red[q]); c2 = fminf(c2, red[q]); }
        g_c[b] = c;
        g_c2[b] = c2;
    }
}

// K2b: factor arrays, full-GPU spread (64 blocks, 1 elt/thread)
__global__ void __launch_bounds__(256) factors_kernel() {
    int i = blockIdx.x * 256 + threadIdx.x;
    int b = i >> 11;
    float c = g_c[b], c2 = g_c2[b];
    float s1 = g_s1[i];
    float u  = s1 + c;
    float u2 = s1 + c2;
    float lr_u  = (u  > 0.f) ? u  : ALPHA_ * u;
    float lr_u2 = (u2 > 0.f) ? u2 : ALPHA_ * u2;
    float mm = fmaxf(lr_u2, lr_u - 60.f);
    g_A [i] = expf(u - mm);
    g_Ap[i] = expf(ALPHA_ * u - mm);
    float v = g_s2[i] - c;
    g_B [i] = expf(v);
    g_Bp[i] = expf(ALPHA_ * v);
}

// ---------------------------------------------------------------------------
// K3: attention via HMMA, warp-specialized, 2-stage pipeline with cp.async
// adj prefetch (thread-private smem slots, no barrier needed for adj).
// 256 blocks x 384 thr = 8 producer warps + 4 consumer warps (m32 x f32).
// ---------------------------------------------------------------------------
static constexpr uint32_t STG    = 32768;   // Phi 8K | Plo 8K | Hhi 8K | Hlo 8K
static constexpr uint32_t O_PHI  = 0;
static constexpr uint32_t O_PLO  = 8192;
static constexpr uint32_t O_HHI  = 16384;
static constexpr uint32_t O_HLO  = 24576;
static constexpr uint32_t OFF_ADJ= 65536;   // 2 x 16384, thread-private slots
static constexpr uint32_t OFF_A  = 98304;   // 256B (64 floats)
static constexpr uint32_t OFF_AP = 98560;   // 256B
static constexpr uint32_t OFF_L  = 98816;   // 256B
static constexpr uint32_t DSMEM  = 99072;

// truncation split: hi = trunc-bf16(p) (p >= 0), lo = p - hi exact, RN on lo
__device__ __forceinline__ uint32_t prmt_hi(uint32_t u0, uint32_t u1) {
    uint32_t r;
    asm("prmt.b32 %0, %1, %2, 0x7632;" : "=r"(r) : "r"(u0), "r"(u1));
    return r;
}

// issue adj(cidx) cp.async into thread-private interleaved slots + commit
__device__ __forceinline__ void adj_prefetch(
    uint32_t sb, const int* __restrict__ adj, int i0, int cidx, int t, int w, int lane)
{
    uint32_t slot = sb + OFF_ADJ + (uint32_t)(cidx & 1) * 16384;
    int rbase = w * 8 + (lane >> 3) * 2;
    int jg = lane & 7;
    int jc = cidx * 64;
    #pragma unroll
    for (int rr = 0; rr < 2; ++rr) {
        const int* src = adj + (size_t)(i0 + rbase + rr) * N_ + jc + jg * 8;
        #pragma unroll
        for (int hh = 0; hh < 2; ++hh) {
            int k = rr * 2 + hh;
            CP16(slot + (uint32_t)(k * 256 + t) * 16, src + hh * 4);
        }
    }
    CP_COMMIT();
}

// Producer body for chunk cidx (threads t < 256). Caller handles EMPTY sync.
// cp.async group queue on entry: [adj(cidx)] outstanding (committed earlier).
__device__ __forceinline__ void produce_chunk(
    char* sm, uint32_t sb, const int* __restrict__ adj,
    int i0, int b, int cidx, int t, int w, int lane,
    const float* sA, const float* sAp, float* lp)
{
    int st = cidx & 1;
    uint32_t stg = sb + (uint32_t)st * STG;
    char*   stgp = sm + (uint32_t)st * STG;
    int jc = cidx * 64;

    // H tiles: cp.async (group: H(cidx))
    {
        int f = t >> 2;
        int q0 = (t & 3) * 2;
        #pragma unroll
        for (int hp = 0; hp < 2; ++hp) {
            int q2 = q0 + hp;
            size_t src = ((size_t)(b * F_ + f)) * N_ + jc + q2 * 8;
            uint32_t sw = ((uint32_t)f * 128 + (uint32_t)q2 * 16) ^ (((uint32_t)(f & 7)) << 4);
            CP16(stg + O_HHI + sw, g_hT_hi + src);
            CP16(stg + O_HLO + sw, g_hT_lo + src);
        }
        CP_COMMIT();
    }

    // wait adj(cidx): queue [adj(cidx), H(cidx)] -> allow 1 outstanding
    CP_WAIT1();

    // prefetch adj(cidx+1) (own slot; no cross-thread hazard)
    bool more = (cidx + 1 < NCH);
    if (more) adj_prefetch(sb, adj, i0, cidx + 1, t, w, lane);

    // P tiles from adj smem: warp w rows w*8..+7; thread: 2 rows x 8 j
    uint32_t aslot = sb + OFF_ADJ + (uint32_t)st * 16384;
    int rbase = w * 8 + (lane >> 3) * 2;
    int jg = lane & 7;
    const float4* Bg  = (const float4*)(g_B  + b * N_ + jc + jg * 8);
    const float4* Bpg = (const float4*)(g_Bp + b * N_ + jc + jg * 8);
    float4 Bv0 = __ldg(Bg);
    float4 Bv1 = __ldg(Bg + 1);
    float4 Bp0 = __ldg(Bpg);
    float4 Bp1 = __ldg(Bpg + 1);
    #pragma unroll
    for (int rr = 0; rr < 2; ++rr) {
        int R = rbase + rr;
        int4 a0, a1;
        asm volatile("ld.shared.v4.b32 {%0,%1,%2,%3}, [%4];"
            : "=r"(a0.x), "=r"(a0.y), "=r"(a0.z), "=r"(a0.w)
            : "r"(aslot + (uint32_t)((rr * 2 + 0) * 256 + t) * 16));
        asm volatile("ld.shared.v4.b32 {%0,%1,%2,%3}, [%4];"
            : "=r"(a1.x), "=r"(a1.y), "=r"(a1.z), "=r"(a1.w)
            : "r"(aslot + (uint32_t)((rr * 2 + 1) * 256 + t) * 16));
        float Ar = sA[R], Apr = sAp[R];
        float p0 = (a0.x > 0) ? fmaxf(Ar * Bv0.x, Apr * Bp0.x) : 0.f;
        float p1 = (a0.y > 0) ? fmaxf(Ar * Bv0.y, Apr * Bp0.y) : 0.f;
        float p2 = (a0.z > 0) ? fmaxf(Ar * Bv0.z, Apr * Bp0.z) : 0.f;
        float p3 = (a0.w > 0) ? fmaxf(Ar * Bv0.w, Apr * Bp0.w) : 0.f;
        float p4 = (a1.x > 0) ? fmaxf(Ar * Bv1.x, Apr * Bp1.x) : 0.f;
        float p5 = (a1.y > 0) ? fmaxf(Ar * Bv1.y, Apr * Bp1.y) : 0.f;
        float p6 = (a1.z > 0) ? fmaxf(Ar * Bv1.z, Apr * Bp1.z) : 0.f;
        float p7 = (a1.w > 0) ? fmaxf(Ar * Bv1.w, Apr * Bp1.w) : 0.f;
        lp[rr] += ((p0 + p1) + (p2 + p3)) + ((p4 + p5) + (p6 + p7));

        uint32_t u0 = __float_as_uint(p0), u1 = __float_as_uint(p1);
        uint32_t u2 = __float_as_uint(p2), u3 = __float_as_uint(p3);
        uint32_t u4 = __float_as_uint(p4), u5 = __float_as_uint(p5);
        uint32_t u6 = __float_as_uint(p6), u7 = __float_as_uint(p7);
        uint32_t h01 = prmt_hi(u0, u1), h23 = prmt_hi(u2, u3);
        uint32_t h45 = prmt_hi(u4, u5), h67 = prmt_hi(u6, u7);
        float lo0 = p0 - __uint_as_float(u0 & 0xFFFF0000u);
        float lo1 = p1 - __uint_as_float(u1 & 0xFFFF0000u);
        float lo2 = p2 - __uint_as_float(u2 & 0xFFFF0000u);
        float lo3 = p3 - __uint_as_float(u3 & 0xFFFF0000u);
        float lo4 = p4 - __uint_as_float(u4 & 0xFFFF0000u);
        float lo5 = p5 - __uint_as_float(u5 & 0xFFFF0000u);
        float lo6 = p6 - __uint_as_float(u6 & 0xFFFF0000u);
        float lo7 = p7 - __uint_as_float(u7 & 0xFFFF0000u);
        __nv_bfloat162 l01 = __float22bfloat162_rn(make_float2(lo0, lo1));
        __nv_bfloat162 l23 = __float22bfloat162_rn(make_float2(lo2, lo3));
        __nv_bfloat162 l45 = __float22bfloat162_rn(make_float2(lo4, lo5));
        __nv_bfloat162 l67 = __float22bfloat162_rn(make_float2(lo6, lo7));

        uint32_t boff = (uint32_t)R * 128 + (uint32_t)jg * 16;
        uint32_t sw = boff ^ (((uint32_t)(R & 7)) << 4);
        *(uint4*)(stgp + O_PHI + sw) = make_uint4(h01, h23, h45, h67);
        *(uint4*)(stgp + O_PLO + sw) =
            make_uint4(*(uint32_t*)&l01, *(uint32_t*)&l23, *(uint32_t*)&l45, *(uint32_t*)&l67);
    }

    // ensure H(cidx) landed: outstanding allowed = adj(cidx+1) if issued
    if (more) CP_WAIT1(); else CP_WAIT0();
}

__global__ void __launch_bounds__(384, 2) attn_kernel(
    const int* __restrict__ adj, float* __restrict__ out)
{
    extern __shared__ __align__(128) char sm[];
    uint32_t sb = smem_u32(sm);

    int t = threadIdx.x, w = t >> 5, lane = t & 31;
    int i0 = blockIdx.x * TI;
    int b = i0 >> 11;

    float* sA  = (float*)(sm + OFF_A);
    float* sAp = (float*)(sm + OFF_AP);
    float* sL  = (float*)(sm + OFF_L);
    if (t < 64) { sA[t] = g_A[i0 + t]; sAp[t] = g_Ap[i0 + t]; }
    __syncthreads();

    if (w < 8) {
        // ---------------- producers ----------------
        float lp[2] = {0.f, 0.f};
        adj_prefetch(sb, adj, i0, 0, t, w, lane);     // adj(0) in flight
        for (int c = 0; c < NCH; ++c) {
            if (c >= 2) BAR_SYNC(4 + (c & 1));        // stage free?
            produce_chunk(sm, sb, adj, i0, b, c, t, w, lane, sA, sAp, lp);
            BAR_ARRIVE(1 + (c & 1));                  // stage full
        }
        // denominators: reduce over 8 j-lanes, publish to sL
        int rbase = w * 8 + (lane >> 3) * 2;
        #pragma unroll
        for (int rr = 0; rr < 2; ++rr) {
            float v = lp[rr];
            v += __shfl_xor_sync(0xffffffffu, v, 1);
            v += __shfl_xor_sync(0xffffffffu, v, 2);
            v += __shfl_xor_sync(0xffffffffu, v, 4);
            if ((lane & 7) == 0) {
                sL[rbase + rr] = v;
                if (!(v >= 1e-20f)) {
                    int si = atomicAdd(&g_nbad, 1);
                    g_bad[si] = i0 + rbase + rr;
                }
            }
        }
        BAR_ARRIVE(7);                                // denominators ready
    } else {
        // ---------------- consumers (4 warps, m32 x f32) ----------------
        float C[2][4][4];
        #pragma unroll
        for (int mt = 0; mt < 2; ++mt)
            #pragma unroll
            for (int g = 0; g < 4; ++g)
                #pragma unroll
                for (int qq = 0; qq < 4; ++qq) C[mt][g][qq] = 0.f;

        int cw = w - 8;
        int m0 = (cw & 1) * 32;
        int f0 = (cw >> 1) * 32;

        for (int c = 0; c < NCH; ++c) {
            BAR_SYNC(1 + (c & 1));                    // stage full?
            uint32_t stg = sb + (uint32_t)(c & 1) * STG;
            #pragma unroll
            for (int ks = 0; ks < 4; ++ks) {
                uint32_t ahi[2][4], alo[2][4];
                #pragma unroll
                for (int mt = 0; mt < 2; ++mt) {
                    int arow = m0 + mt * 16 + (lane & 15);
                    uint32_t aoff = (uint32_t)arow * 128 + (uint32_t)ks * 32 + ((uint32_t)(lane >> 4)) * 16;
                    uint32_t asw = aoff ^ (((uint32_t)(arow & 7)) << 4);
                    LDSM4(ahi[mt], stg + O_PHI + asw);
                    LDSM4(alo[mt], stg + O_PLO + asw);
                }
                #pragma unroll
                for (int nb = 0; nb < 2; ++nb) {
                    uint32_t bhi[4], blo[4];
                    int nrow = f0 + nb * 16 + (lane & 15);
                    uint32_t boff = (uint32_t)nrow * 128 + (uint32_t)ks * 32 + ((uint32_t)(lane >> 4)) * 16;
                    uint32_t bsw = boff ^ (((uint32_t)(nrow & 7)) << 4);
                    LDSM4(bhi, stg + O_HHI + bsw);
                    LDSM4(blo, stg + O_HLO + bsw);
                    #pragma unroll
                    for (int mt = 0; mt < 2; ++mt) {
                        MMA_BF16(C[mt][nb * 2],     ahi[mt], bhi[0], bhi[2]);
                        MMA_BF16(C[mt][nb * 2 + 1], ahi[mt], bhi[1], bhi[3]);
                        MMA_BF16(C[mt][nb * 2],     ahi[mt], blo[0], blo[2]);
                        MMA_BF16(C[mt][nb * 2 + 1], ahi[mt], blo[1], blo[3]);
                        MMA_BF16(C[mt][nb * 2],     alo[mt], bhi[0], bhi[2]);
                        MMA_BF16(C[mt][nb * 2 + 1], alo[mt], bhi[1], bhi[3]);
                    }
                }
            }
            BAR_ARRIVE(4 + (c & 1));                  // stage empty
        }

        BAR_SYNC(7);                                  // denominators ready

        // epilogue: normalize, ELU, write out directly
        int fo = f0 + (lane & 3) * 2;
        #pragma unroll
        for (int mt = 0; mt < 2; ++mt) {
            int lr0 = m0 + mt * 16 + (lane >> 2);
            float inv0 = 1.f / sL[lr0];
            float inv1 = 1.f / sL[lr0 + 8];
            float* o0 = out + (size_t)(i0 + lr0) * F_ + fo;
            float* o1 = o0 + 8 * F_;
            #pragma unroll
            for (int g = 0; g < 4; ++g) {
                float a0 = C[mt][g][0] * inv0, a1 = C[mt][g][1] * inv0;
                float b0 = C[mt][g][2] * inv1, b1 = C[mt][g][3] * inv1;
                a0 = (a0 > 0.f) ? a0 : (__expf(a0) - 1.f);
                a1 = (a1 > 0.f) ? a1 : (__expf(a1) - 1.f);
                b0 = (b0 > 0.f) ? b0 : (__expf(b0) - 1.f);
                b1 = (b1 > 0.f) ? b1 : (__expf(b1) - 1.f);
                *(float2*)(o0 + g * 8) = make_float2(a0, a1);
                *(float2*)(o1 + g * 8) = make_float2(b0, b1);
            }
        }
    }
}

// ---------------------------------------------------------------------------
// K4: exact fp32 recompute of flagged rows
// ---------------------------------------------------------------------------
__global__ void __launch_bounds__(256) fallback_kernel(
    const int* __restrict__ adj, float* __restrict__ out)
{
    __shared__ float p_s[N_];
    __shared__ float red[4][64];
    __shared__ float lred[8];
    int t = threadIdx.x, w = t >> 5, lane = t & 31;
    int nb = g_nbad;
    for (int k = blockIdx.x; k < nb; k += gridDim.x) {
        int row = g_bad[k];
        int b = row >> 11;
        float A = g_A[row], Ap = g_Ap[row];
        float lpv = 0.f;
        for (int j = t; j < N_; j += 256) {
            int av = adj[(size_t)row * N_ + j];
            float p = (av > 0) ? fmaxf(A * g_B[b * N_ + j], Ap * g_Bp[b * N_ + j]) : 0.f;
            p_s[j] = p;
            lpv += p;
        }
        #pragma unroll
        for (int off = 16; off; off >>= 1) lpv += __shfl_xor_sync(0xffffffffu, lpv, off);
        if (lane == 0) lred[w] = lpv;
        __syncthreads();
        float l = 0.f;
        #pragma unroll
        for (int q = 0; q < 8; ++q) l += lred[q];
        int f = t & 63, seg = t >> 6;
        float acc = 0.f;
        const float* hb = g_h + ((size_t)b * N_ + seg * 512) * F_ + f;
        for (int j = 0; j < 512; ++j) acc = fmaf(p_s[seg * 512 + j], hb[(size_t)j * F_], acc);
        red[seg][f] = acc;
        __syncthreads();
        if (t < 64) {
            float v = (red[0][t] + red[1][t] + red[2][t] + red[3][t]) / l;
            out[(size_t)row * F_ + t] = (v > 0.f) ? v : (__expf(v) - 1.f);
        }
        __syncthreads();
    }
}

extern "C" void kernel_launch(void* const* d_in, const int* in_sizes, int n_in,
                              void* d_out, int out_size)
{
    const float* x   = (const float*)d_in[0];
    const int*   adj = (const int*)  d_in[1];
    const float* W   = (const float*)d_in[2];
    const float* a   = (const float*)d_in[3];
    float* out = (float*)d_out;

    cudaFuncSetAttribute(attn_kernel, cudaFuncAttributeMaxDynamicSharedMemorySize, DSMEM);

    prep_kernel<<<(B_ * N_) / 16, 1024>>>(x, W, a);
    cmax_kernel<<<B_, 256>>>();
    factors_kernel<<<(B_ * N_) / 256, 256>>>();
    attn_kernel<<<B_ * N_ / TI, 384, DSMEM>>>(adj, out);
    fallback_kernel<<<64, 256>>>(adj, out);
}

// round 15
// speedup vs baseline: 1.0626x; 1.0626x over previous
#include <cuda_runtime.h>
#include <cuda_bf16.h>
#include <cstdint>

static constexpr int B_ = 8;
static constexpr int N_ = 2048;
static constexpr int F_ = 64;
static constexpr float ALPHA_ = 0.2f;
static constexpr int NCH = N_ / 64;      // 32 chunks, full j-range per block
static constexpr int TI = 64;            // rows per block

// -------- scratch (no cudaMalloc allowed) --------
__device__ float g_h[B_ * N_ * F_];
__device__ float g_s1[B_ * N_];
__device__ float g_s2[B_ * N_];
__device__ float g_A [B_ * N_];
__device__ float g_Ap[B_ * N_];
__device__ float g_B [B_ * N_];
__device__ float g_Bp[B_ * N_];
__device__ __nv_bfloat16 g_hT_hi[B_ * F_ * N_];   // [b][f][n]
__device__ __nv_bfloat16 g_hT_lo[B_ * F_ * N_];
__device__ int g_nbad;
__device__ int g_bad[B_ * N_];

__device__ __forceinline__ uint32_t smem_u32(const void* p) {
    uint32_t a;
    asm("{ .reg .u64 t; cvta.to.shared.u64 t, %1; cvt.u32.u64 %0, t; }" : "=r"(a) : "l"(p));
    return a;
}

#define LDSM4(r, addr) \
    asm volatile("ldmatrix.sync.aligned.m8n8.x4.shared.b16 {%0,%1,%2,%3}, [%4];" \
        : "=r"((r)[0]), "=r"((r)[1]), "=r"((r)[2]), "=r"((r)[3]) : "r"(addr))

#define MMA_BF16(C, a, b0, b1) \
    asm volatile("mma.sync.aligned.m16n8k16.row.col.f32.bf16.bf16.f32 " \
        "{%0,%1,%2,%3}, {%4,%5,%6,%7}, {%8,%9}, {%0,%1,%2,%3};" \
        : "+f"((C)[0]), "+f"((C)[1]), "+f"((C)[2]), "+f"((C)[3]) \
        : "r"((a)[0]), "r"((a)[1]), "r"((a)[2]), "r"((a)[3]), "r"(b0), "r"(b1))

#define CP16(dst, src) \
    asm volatile("cp.async.cg.shared.global [%0], [%1], 16;" :: "r"(dst), "l"(src))
#define CP_COMMIT()  asm volatile("cp.async.commit_group;" ::: "memory")
#define CP_WAIT0()   asm volatile("cp.async.wait_group 0;" ::: "memory")
#define CP_WAIT1()   asm volatile("cp.async.wait_group 1;" ::: "memory")

// named block barriers (384 participants: 256 producer + 128 consumer threads)
#define BAR_SYNC(id)   asm volatile("bar.sync %0, 384;"   :: "r"(id) : "memory")
#define BAR_ARRIVE(id) asm volatile("bar.arrive %0, 384;" :: "r"(id) : "memory")

// ---------------------------------------------------------------------------
// K1: h = x@W ; s1,s2 ; transposed bf16 hi/lo copies of h
// ---------------------------------------------------------------------------
__global__ void __launch_bounds__(1024) prep_kernel(
    const float* __restrict__ x, const float* __restrict__ W, const float* __restrict__ a)
{
    __shared__ float W_s[F_ * F_];
    __shared__ float x_s[16][F_];
    __shared__ float h_sh[16][F_ + 1];
    __shared__ float red[16][2][2];

    int t = threadIdx.x, tx = t & 63, ty = t >> 6;
    int row0 = blockIdx.x * 16;
    int row = row0 + ty;

    #pragma unroll
    for (int k = 0; k < 4; ++k) W_s[t + k * 1024] = W[t + k * 1024];
    x_s[ty][tx] = x[(size_t)row * F_ + tx];
    __syncthreads();

    float h = 0.f;
    #pragma unroll
    for (int k = 0; k < F_; ++k) h = fmaf(x_s[ty][k], W_s[k * F_ + tx], h);
    g_h[(size_t)row * F_ + tx] = h;
    h_sh[ty][tx] = h;

    float v1 = h * a[tx];
    float v2 = h * a[F_ + tx];
    #pragma unroll
    for (int off = 16; off; off >>= 1) {
        v1 += __shfl_xor_sync(0xffffffffu, v1, off);
        v2 += __shfl_xor_sync(0xffffffffu, v2, off);
    }
    if ((tx & 31) == 0) { red[ty][tx >> 5][0] = v1; red[ty][tx >> 5][1] = v2; }
    __syncthreads();
    if (tx == 0) {
        g_s1[row] = red[ty][0][0] + red[ty][1][0];
        g_s2[row] = red[ty][0][1] + red[ty][1][1];
    }

    int f = t >> 4, rr = t & 15;
    float v = h_sh[rr][f];
    __nv_bfloat16 hi = __float2bfloat16(v);
    float lov = v - __bfloat162float(hi);
    int b = row0 >> 11;
    size_t o = ((size_t)(b * F_ + f)) * N_ + (row0 & (N_ - 1)) + rr;
    g_hT_hi[o] = hi;
    g_hT_lo[o] = __float2bfloat16(lov);
}

// ---------------------------------------------------------------------------
// K2: factors (merged). 64 blocks; each block redundantly reduces its batch's
// s2 (c = max of warp maxes, c2 = min of warp maxes), then computes its slice.
// ---------------------------------------------------------------------------
__global__ void __launch_bounds__(256) factors_kernel() {
    __shared__ float red[8];
    int t = threadIdx.x, w = t >> 5, lane = t & 31;
    int i = blockIdx.x * 256 + t;
    int b = blockIdx.x >> 3;
    if (i == 0) g_nbad = 0;

    float m = -3.4e38f;
    for (int k = t; k < N_; k += 256) m = fmaxf(m, g_s2[b * N_ + k]);
    #pragma unroll
    for (int off = 16; off; off >>= 1) m = fmaxf(m, __shfl_xor_sync(0xffffffffu, m, off));
    if (lane == 0) red[w] = m;
    __syncthreads();
    float c = -3.4e38f, c2 = 3.4e38f;
    #pragma unroll
    for (int q = 0; q < 8; ++q) { c = fmaxf(c, red[q]); c2 = fminf(c2, red[q]); }

    float s1 = g_s1[i];
    float u  = s1 + c;
    float u2 = s1 + c2;
    float lr_u  = (u  > 0.f) ? u  : ALPHA_ * u;
    float lr_u2 = (u2 > 0.f) ? u2 : ALPHA_ * u2;
    float mm = fmaxf(lr_u2, lr_u - 60.f);
    g_A [i] = expf(u - mm);
    g_Ap[i] = expf(ALPHA_ * u - mm);
    float v = g_s2[i] - c;
    g_B [i] = expf(v);
    g_Bp[i] = expf(ALPHA_ * v);
}

// ---------------------------------------------------------------------------
// K3: attention via HMMA, warp-specialized, 3-stage named-barrier pipeline.
// 256 blocks x 384 thr: warps 0-7 producers (adj __ldcs -> P split -> smem,
// denominators), warps 8-11 consumers (H cp.async staging + LDSM + MMA m32xf32
// + direct epilogue).
// ---------------------------------------------------------------------------
static constexpr uint32_t STG    = 32768;   // Phi 8K | Plo 8K | Hhi 8K | Hlo 8K
static constexpr uint32_t O_PHI  = 0;
static constexpr uint32_t O_PLO  = 8192;
static constexpr uint32_t O_HHI  = 16384;
static constexpr uint32_t O_HLO  = 24576;
static constexpr uint32_t OFF_A  = 98304;   // 256B (64 floats)
static constexpr uint32_t OFF_AP = 98560;   // 256B
static constexpr uint32_t OFF_L  = 98816;   // 256B
static constexpr uint32_t DSMEM  = 99072;

// truncation split: hi = trunc-bf16(p) (p >= 0), lo = p - hi exact, RN on lo
__device__ __forceinline__ uint32_t prmt_hi(uint32_t u0, uint32_t u1) {
    uint32_t r;
    asm("prmt.b32 %0, %1, %2, 0x7632;" : "=r"(r) : "r"(u0), "r"(u1));
    return r;
}

// Producer: produce P(cidx) into stage[cidx%3]. Threads t < 256 only.
__device__ __forceinline__ void produce_chunk(
    char* sm, uint32_t sb, const int* __restrict__ adj,
    int i0, int b, int cidx, int t, int w, int lane,
    const float* sA, const float* sAp, float* lp)
{
    int st = cidx % 3;
    char* stgp = sm + (uint32_t)st * STG;
    int jc = cidx * 64;

    // P tiles: warp w rows w*8..+7; thread: 2 rows x 8 j
    int rbase = w * 8 + (lane >> 3) * 2;
    int jg = lane & 7;
    const float4* Bg  = (const float4*)(g_B  + b * N_ + jc + jg * 8);
    const float4* Bpg = (const float4*)(g_Bp + b * N_ + jc + jg * 8);
    float4 Bv0 = __ldg(Bg);
    float4 Bv1 = __ldg(Bg + 1);
    float4 Bp0 = __ldg(Bpg);
    float4 Bp1 = __ldg(Bpg + 1);
    #pragma unroll
    for (int rr = 0; rr < 2; ++rr) {
        int R = rbase + rr;
        const int4* ap = (const int4*)(adj + (size_t)(i0 + R) * N_ + jc + jg * 8);
        int4 a0 = __ldcs(ap);
        int4 a1 = __ldcs(ap + 1);
        float Ar = sA[R], Apr = sAp[R];
        float p0 = (a0.x > 0) ? fmaxf(Ar * Bv0.x, Apr * Bp0.x) : 0.f;
        float p1 = (a0.y > 0) ? fmaxf(Ar * Bv0.y, Apr * Bp0.y) : 0.f;
        float p2 = (a0.z > 0) ? fmaxf(Ar * Bv0.z, Apr * Bp0.z) : 0.f;
        float p3 = (a0.w > 0) ? fmaxf(Ar * Bv0.w, Apr * Bp0.w) : 0.f;
        float p4 = (a1.x > 0) ? fmaxf(Ar * Bv1.x, Apr * Bp1.x) : 0.f;
        float p5 = (a1.y > 0) ? fmaxf(Ar * Bv1.y, Apr * Bp1.y) : 0.f;
        float p6 = (a1.z > 0) ? fmaxf(Ar * Bv1.z, Apr * Bp1.z) : 0.f;
        float p7 = (a1.w > 0) ? fmaxf(Ar * Bv1.w, Apr * Bp1.w) : 0.f;
        lp[rr] += ((p0 + p1) + (p2 + p3)) + ((p4 + p5) + (p6 + p7));

        uint32_t u0 = __float_as_uint(p0), u1 = __float_as_uint(p1);
        uint32_t u2 = __float_as_uint(p2), u3 = __float_as_uint(p3);
        uint32_t u4 = __float_as_uint(p4), u5 = __float_as_uint(p5);
        uint32_t u6 = __float_as_uint(p6), u7 = __float_as_uint(p7);
        uint32_t h01 = prmt_hi(u0, u1), h23 = prmt_hi(u2, u3);
        uint32_t h45 = prmt_hi(u4, u5), h67 = prmt_hi(u6, u7);
        float lo0 = p0 - __uint_as_float(u0 & 0xFFFF0000u);
        float lo1 = p1 - __uint_as_float(u1 & 0xFFFF0000u);
        float lo2 = p2 - __uint_as_float(u2 & 0xFFFF0000u);
        float lo3 = p3 - __uint_as_float(u3 & 0xFFFF0000u);
        float lo4 = p4 - __uint_as_float(u4 & 0xFFFF0000u);
        float lo5 = p5 - __uint_as_float(u5 & 0xFFFF0000u);
        float lo6 = p6 - __uint_as_float(u6 & 0xFFFF0000u);
        float lo7 = p7 - __uint_as_float(u7 & 0xFFFF0000u);
        __nv_bfloat162 l01 = __float22bfloat162_rn(make_float2(lo0, lo1));
        __nv_bfloat162 l23 = __float22bfloat162_rn(make_float2(lo2, lo3));
        __nv_bfloat162 l45 = __float22bfloat162_rn(make_float2(lo4, lo5));
        __nv_bfloat162 l67 = __float22bfloat162_rn(make_float2(lo6, lo7));

        uint32_t boff = (uint32_t)R * 128 + (uint32_t)jg * 16;
        uint32_t sw = boff ^ (((uint32_t)(R & 7)) << 4);
        *(uint4*)(stgp + O_PHI + sw) = make_uint4(h01, h23, h45, h67);
        *(uint4*)(stgp + O_PLO + sw) =
            make_uint4(*(uint32_t*)&l01, *(uint32_t*)&l23, *(uint32_t*)&l45, *(uint32_t*)&l67);
    }
}

// Consumer-side H staging: 128 threads (ct = t-256), 8 CP16 each + commit.
__device__ __forceinline__ void stage_H(
    uint32_t sb, int b, int cidx, int ct)
{
    uint32_t stg = sb + (uint32_t)(cidx % 3) * STG;
    int jc = cidx * 64;
    int f = ct >> 1;
    int q0 = (ct & 1) * 4;
    #pragma unroll
    for (int hp = 0; hp < 4; ++hp) {
        int q2 = q0 + hp;
        size_t src = ((size_t)(b * F_ + f)) * N_ + jc + q2 * 8;
        uint32_t sw = ((uint32_t)f * 128 + (uint32_t)q2 * 16) ^ (((uint32_t)(f & 7)) << 4);
        CP16(stg + O_HHI + sw, g_hT_hi + src);
        CP16(stg + O_HLO + sw, g_hT_lo + src);
    }
    CP_COMMIT();
}

__global__ void __launch_bounds__(384, 2) attn_kernel(
    const int* __restrict__ adj, float* __restrict__ out)
{
    extern __shared__ __align__(128) char sm[];
    uint32_t sb = smem_u32(sm);

    int t = threadIdx.x, w = t >> 5, lane = t & 31;
    int i0 = blockIdx.x * TI;
    int b = i0 >> 11;

    float* sA  = (float*)(sm + OFF_A);
    float* sAp = (float*)(sm + OFF_AP);
    float* sL  = (float*)(sm + OFF_L);
    if (t < 64) { sA[t] = g_A[i0 + t]; sAp[t] = g_Ap[i0 + t]; }
    __syncthreads();

    if (w < 8) {
        // ---------------- producers ----------------
        float lp[2] = {0.f, 0.f};
        for (int c = 0; c < NCH; ++c) {
            if (c >= 3) BAR_SYNC(4 + (c % 3));         // stage free?
            produce_chunk(sm, sb, adj, i0, b, c, t, w, lane, sA, sAp, lp);
            BAR_ARRIVE(1 + (c % 3));                   // P(c) ready
        }
        // denominators: reduce over 8 j-lanes, publish to sL
        int rbase = w * 8 + (lane >> 3) * 2;
        #pragma unroll
        for (int rr = 0; rr < 2; ++rr) {
            float v = lp[rr];
            v += __shfl_xor_sync(0xffffffffu, v, 1);
            v += __shfl_xor_sync(0xffffffffu, v, 2);
            v += __shfl_xor_sync(0xffffffffu, v, 4);
            if ((lane & 7) == 0) {
                sL[rbase + rr] = v;
                if (!(v >= 1e-20f)) {
                    int si = atomicAdd(&g_nbad, 1);
                    g_bad[si] = i0 + rbase + rr;
                }
            }
        }
        BAR_ARRIVE(7);                                 // denominators ready
    } else {
        // ---------------- consumers (4 warps, m32 x f32 + H staging) --------
        int ct = t - 256;
        float C[2][4][4];
        #pragma unroll
        for (int mt = 0; mt < 2; ++mt)
            #pragma unroll
            for (int g = 0; g < 4; ++g)
                #pragma unroll
                for (int qq = 0; qq < 4; ++qq) C[mt][g][qq] = 0.f;

        int cw = w - 8;
        int m0 = (cw & 1) * 32;
        int f0 = (cw >> 1) * 32;

        stage_H(sb, b, 0, ct);   // H(0) in flight

        for (int c = 0; c < NCH; ++c) {
            BAR_SYNC(1 + (c % 3));                     // P(c) ready?
            // stage H(c+1): safe — all consumers done with MMA(c-2) (that
            // stage's prior H), and producers touch only the P region.
            if (c + 1 < NCH) { stage_H(sb, b, c + 1, ct); CP_WAIT1(); }
            else CP_WAIT0();                           // H(c) landed

            uint32_t stg = sb + (uint32_t)(c % 3) * STG;
            #pragma unroll
            for (int ks = 0; ks < 4; ++ks) {
                uint32_t ahi[2][4], alo[2][4];
                #pragma unroll
                for (int mt = 0; mt < 2; ++mt) {
                    int arow = m0 + mt * 16 + (lane & 15);
                    uint32_t aoff = (uint32_t)arow * 128 + (uint32_t)ks * 32 + ((uint32_t)(lane >> 4)) * 16;
                    uint32_t asw = aoff ^ (((uint32_t)(arow & 7)) << 4);
                    LDSM4(ahi[mt], stg + O_PHI + asw);
                    LDSM4(alo[mt], stg + O_PLO + asw);
                }
                #pragma unroll
                for (int nb = 0; nb < 2; ++nb) {
                    uint32_t bhi[4], blo[4];
                    int nrow = f0 + nb * 16 + (lane & 15);
                    uint32_t boff = (uint32_t)nrow * 128 + (uint32_t)ks * 32 + ((uint32_t)(lane >> 4)) * 16;
                    uint32_t bsw = boff ^ (((uint32_t)(nrow & 7)) << 4);
                    LDSM4(bhi, stg + O_HHI + bsw);
                    LDSM4(blo, stg + O_HLO + bsw);
                    #pragma unroll
                    for (int mt = 0; mt < 2; ++mt) {
                        MMA_BF16(C[mt][nb * 2],     ahi[mt], bhi[0], bhi[2]);
                        MMA_BF16(C[mt][nb * 2 + 1], ahi[mt], bhi[1], bhi[3]);
                        MMA_BF16(C[mt][nb * 2],     ahi[mt], blo[0], blo[2]);
                        MMA_BF16(C[mt][nb * 2 + 1], ahi[mt], blo[1], blo[3]);
                        MMA_BF16(C[mt][nb * 2],     alo[mt], bhi[0], bhi[2]);
                        MMA_BF16(C[mt][nb * 2 + 1], alo[mt], bhi[1], bhi[3]);
                    }
                }
            }
            BAR_ARRIVE(4 + (c % 3));                   // stage empty
        }

        BAR_SYNC(7);                                   // denominators ready

        // epilogue: normalize, ELU, write out directly
        int fo = f0 + (lane & 3) * 2;
        #pragma unroll
        for (int mt = 0; mt < 2; ++mt) {
            int lr0 = m0 + mt * 16 + (lane >> 2);
            float inv0 = 1.f / sL[lr0];
            float inv1 = 1.f / sL[lr0 + 8];
            float* o0 = out + (size_t)(i0 + lr0) * F_ + fo;
            float* o1 = o0 + 8 * F_;
            #pragma unroll
            for (int g = 0; g < 4; ++g) {
                float a0 = C[mt][g][0] * inv0, a1 = C[mt][g][1] * inv0;
                float b0 = C[mt][g][2] * inv1, b1 = C[mt][g][3] * inv1;
                a0 = (a0 > 0.f) ? a0 : (__expf(a0) - 1.f);
                a1 = (a1 > 0.f) ? a1 : (__expf(a1) - 1.f);
                b0 = (b0 > 0.f) ? b0 : (__expf(b0) - 1.f);
                b1 = (b1 > 0.f) ? b1 : (__expf(b1) - 1.f);
                *(float2*)(o0 + g * 8) = make_float2(a0, a1);
                *(float2*)(o1 + g * 8) = make_float2(b0, b1);
            }
        }
    }
}

// ---------------------------------------------------------------------------
// K4: exact fp32 recompute of flagged rows
// ---------------------------------------------------------------------------
__global__ void __launch_bounds__(256) fallback_kernel(
    const int* __restrict__ adj, float* __restrict__ out)
{
    __shared__ float p_s[N_];
    __shared__ float red[4][64];
    __shared__ float lred[8];
    int t = threadIdx.x, w = t >> 5, lane = t & 31;
    int nb = g_nbad;
    for (int k = blockIdx.x; k < nb; k += gridDim.x) {
        int row = g_bad[k];
        int b = row >> 11;
        float A = g_A[row], Ap = g_Ap[row];
        float lpv = 0.f;
        for (int j = t; j < N_; j += 256) {
            int av = adj[(size_t)row * N_ + j];
            float p = (av > 0) ? fmaxf(A * g_B[b * N_ + j], Ap * g_Bp[b * N_ + j]) : 0.f;
            p_s[j] = p;
            lpv += p;
        }
        #pragma unroll
        for (int off = 16; off; off >>= 1) lpv += __shfl_xor_sync(0xffffffffu, lpv, off);
        if (lane == 0) lred[w] = lpv;
        __syncthreads();
        float l = 0.f;
        #pragma unroll
        for (int q = 0; q < 8; ++q) l += lred[q];
        int f = t & 63, seg = t >> 6;
        float acc = 0.f;
        const float* hb = g_h + ((size_t)b * N_ + seg * 512) * F_ + f;
        for (int j = 0; j < 512; ++j) acc = fmaf(p_s[seg * 512 + j], hb[(size_t)j * F_], acc);
        red[seg][f] = acc;
        __syncthreads();
        if (t < 64) {
            float v = (red[0][t] + red[1][t] + red[2][t] + red[3][t]) / l;
            out[(size_t)row * F_ + t] = (v > 0.f) ? v : (__expf(v) - 1.f);
        }
        __syncthreads();
    }
}

extern "C" void kernel_launch(void* const* d_in, const int* in_sizes, int n_in,
                              void* d_out, int out_size)
{
    const float* x   = (const float*)d_in[0];
    const int*   adj = (const int*)  d_in[1];
    const float* W   = (const float*)d_in[2];
    const float* a   = (const float*)d_in[3];
    float* out = (float*)d_out;

    cudaFuncSetAttribute(attn_kernel, cudaFuncAttributeMaxDynamicSharedMemorySize, DSMEM);

    prep_kernel<<<(B_ * N_) / 16, 1024>>>(x, W, a);
    factors_kernel<<<(B_ * N_) / 256, 256>>>();
    attn_kernel<<<B_ * N_ / TI, 384, DSMEM>>>(adj, out);
    fallback_kernel<<<64, 256>>>(adj, out);
}

// round 16
// speedup vs baseline: 1.1547x; 1.0867x over previous
#include <cuda_runtime.h>
#include <cuda_bf16.h>
#include <cstdint>

static constexpr int B_ = 8;
static constexpr int N_ = 2048;
static constexpr int F_ = 64;
static constexpr float ALPHA_ = 0.2f;
static constexpr int NCH = N_ / 64;      // 32 chunks, full j-range per block
static constexpr int TI = 64;            // rows per block

// -------- scratch (no cudaMalloc allowed) --------
__device__ float g_h[B_ * N_ * F_];
__device__ float g_s1[B_ * N_];
__device__ float g_s2[B_ * N_];
__device__ float g_A [B_ * N_];
__device__ float g_Ap[B_ * N_];
__device__ float g_B [B_ * N_];
__device__ float g_Bp[B_ * N_];
__device__ __nv_bfloat16 g_hT_hi[B_ * F_ * N_];   // [b][f][n]
__device__ __nv_bfloat16 g_hT_lo[B_ * F_ * N_];
__device__ int g_nbad;
__device__ int g_bad[B_ * N_];

__device__ __forceinline__ uint32_t smem_u32(const void* p) {
    uint32_t a;
    asm("{ .reg .u64 t; cvta.to.shared.u64 t, %1; cvt.u32.u64 %0, t; }" : "=r"(a) : "l"(p));
    return a;
}

#define LDSM4(r, addr) \
    asm volatile("ldmatrix.sync.aligned.m8n8.x4.shared.b16 {%0,%1,%2,%3}, [%4];" \
        : "=r"((r)[0]), "=r"((r)[1]), "=r"((r)[2]), "=r"((r)[3]) : "r"(addr))

#define MMA_BF16(C, a, b0, b1) \
    asm volatile("mma.sync.aligned.m16n8k16.row.col.f32.bf16.bf16.f32 " \
        "{%0,%1,%2,%3}, {%4,%5,%6,%7}, {%8,%9}, {%0,%1,%2,%3};" \
        : "+f"((C)[0]), "+f"((C)[1]), "+f"((C)[2]), "+f"((C)[3]) \
        : "r"((a)[0]), "r"((a)[1]), "r"((a)[2]), "r"((a)[3]), "r"(b0), "r"(b1))

#define CP16(dst, src) \
    asm volatile("cp.async.cg.shared.global [%0], [%1], 16;" :: "r"(dst), "l"(src))
#define CP_COMMIT() asm volatile("cp.async.commit_group;" ::: "memory")
#define CP_WAIT0()  asm volatile("cp.async.wait_group 0;" ::: "memory")

// named block barriers (384 participants: 256 producer + 128 consumer threads)
#define BAR_SYNC(id)   asm volatile("bar.sync %0, 384;"   :: "r"(id) : "memory")
#define BAR_ARRIVE(id) asm volatile("bar.arrive %0, 384;" :: "r"(id) : "memory")

// ---------------------------------------------------------------------------
// K1: h = x@W ; s1,s2 ; transposed bf16 hi/lo copies of h
// ---------------------------------------------------------------------------
__global__ void __launch_bounds__(1024) prep_kernel(
    const float* __restrict__ x, const float* __restrict__ W, const float* __restrict__ a)
{
    __shared__ float W_s[F_ * F_];
    __shared__ float x_s[16][F_];
    __shared__ float h_sh[16][F_ + 1];
    __shared__ float red[16][2][2];

    int t = threadIdx.x, tx = t & 63, ty = t >> 6;
    int row0 = blockIdx.x * 16;
    int row = row0 + ty;

    #pragma unroll
    for (int k = 0; k < 4; ++k) W_s[t + k * 1024] = W[t + k * 1024];
    x_s[ty][tx] = x[(size_t)row * F_ + tx];
    __syncthreads();

    float h = 0.f;
    #pragma unroll
    for (int k = 0; k < F_; ++k) h = fmaf(x_s[ty][k], W_s[k * F_ + tx], h);
    g_h[(size_t)row * F_ + tx] = h;
    h_sh[ty][tx] = h;

    float v1 = h * a[tx];
    float v2 = h * a[F_ + tx];
    #pragma unroll
    for (int off = 16; off; off >>= 1) {
        v1 += __shfl_xor_sync(0xffffffffu, v1, off);
        v2 += __shfl_xor_sync(0xffffffffu, v2, off);
    }
    if ((tx & 31) == 0) { red[ty][tx >> 5][0] = v1; red[ty][tx >> 5][1] = v2; }
    __syncthreads();
    if (tx == 0) {
        g_s1[row] = red[ty][0][0] + red[ty][1][0];
        g_s2[row] = red[ty][0][1] + red[ty][1][1];
    }

    int f = t >> 4, rr = t & 15;
    float v = h_sh[rr][f];
    __nv_bfloat16 hi = __float2bfloat16(v);
    float lov = v - __bfloat162float(hi);
    int b = row0 >> 11;
    size_t o = ((size_t)(b * F_ + f)) * N_ + (row0 & (N_ - 1)) + rr;
    g_hT_hi[o] = hi;
    g_hT_lo[o] = __float2bfloat16(lov);
}

// ---------------------------------------------------------------------------
// K2: factors (merged). 64 blocks; each block redundantly reduces its batch's
// s2 (c = max of warp maxes, c2 = min of warp maxes), then computes its slice.
// ---------------------------------------------------------------------------
__global__ void __launch_bounds__(256) factors_kernel() {
    __shared__ float red[8];
    int t = threadIdx.x, w = t >> 5, lane = t & 31;
    int i = blockIdx.x * 256 + t;
    int b = blockIdx.x >> 3;

    float m = -3.4e38f;
    for (int k = t; k < N_; k += 256) m = fmaxf(m, g_s2[b * N_ + k]);
    #pragma unroll
    for (int off = 16; off; off >>= 1) m = fmaxf(m, __shfl_xor_sync(0xffffffffu, m, off));
    if (lane == 0) red[w] = m;
    __syncthreads();
    float c = -3.4e38f, c2 = 3.4e38f;
    #pragma unroll
    for (int q = 0; q < 8; ++q) { c = fmaxf(c, red[q]); c2 = fminf(c2, red[q]); }

    float s1 = g_s1[i];
    float u  = s1 + c;
    float u2 = s1 + c2;
    float lr_u  = (u  > 0.f) ? u  : ALPHA_ * u;
    float lr_u2 = (u2 > 0.f) ? u2 : ALPHA_ * u2;
    float mm = fmaxf(lr_u2, lr_u - 60.f);
    g_A [i] = expf(u - mm);
    g_Ap[i] = expf(ALPHA_ * u - mm);
    float v = g_s2[i] - c;
    g_B [i] = expf(v);
    g_Bp[i] = expf(ALPHA_ * v);
}

// K2b: reset bad counter (keeps attn as the 4th launch for ncu capture)
__global__ void reset_kernel() { if (threadIdx.x == 0) g_nbad = 0; }

// ---------------------------------------------------------------------------
// K3: attention via HMMA, warp-specialized, 3-stage named-barrier pipeline.
// 256 blocks x 384 thr: warps 0-7 producers (H cp.async + adj __ldcs -> P
// truncation-split -> smem + denominators), warps 8-11 consumers
// (LDSM + MMA m32 x f32 + direct epilogue). R13 structure + smem B/Bp.
// ---------------------------------------------------------------------------
static constexpr uint32_t STG    = 32768;   // Phi 8K | Plo 8K | Hhi 8K | Hlo 8K
static constexpr uint32_t O_PHI  = 0;
static constexpr uint32_t O_PLO  = 8192;
static constexpr uint32_t O_HHI  = 16384;
static constexpr uint32_t O_HLO  = 24576;
static constexpr uint32_t OFF_B  = 98304;   // 8KB (N_ floats)
static constexpr uint32_t OFF_BP = 106496;  // 8KB
static constexpr uint32_t OFF_A  = 114688;  // 256B (64 floats)
static constexpr uint32_t OFF_AP = 114944;  // 256B
static constexpr uint32_t OFF_L  = 115200;  // 256B
static constexpr uint32_t DSMEM  = 115456;  // x2 blocks = 225.5KB/SM

// truncation split: hi = trunc-bf16(p) (p >= 0), lo = p - hi exact, RN on lo
__device__ __forceinline__ uint32_t prmt_hi(uint32_t u0, uint32_t u1) {
    uint32_t r;
    asm("prmt.b32 %0, %1, %2, 0x7632;" : "=r"(r) : "r"(u0), "r"(u1));
    return r;
}

// Producer: stage H(cidx) via cp.async + produce P(cidx) into stage[cidx%3].
// Called only by threads t < 256.
__device__ __forceinline__ void produce_chunk(
    char* sm, uint32_t sb, const int* __restrict__ adj,
    int i0, int b, int cidx, int t, int w, int lane,
    const float* sA, const float* sAp, const float* sB, const float* sBp,
    float* lp)
{
    int st = cidx % 3;
    uint32_t stg = sb + (uint32_t)st * STG;
    char*   stgp = sm + (uint32_t)st * STG;
    int jc = cidx * 64;

    // H tiles: 64 f-rows x 64 j bf16 hi/lo, swizzled, via cp.async
    {
        int f = t >> 2;
        int q0 = (t & 3) * 2;
        #pragma unroll
        for (int hp = 0; hp < 2; ++hp) {
            int q2 = q0 + hp;
            size_t src = ((size_t)(b * F_ + f)) * N_ + jc + q2 * 8;
            uint32_t sw = ((uint32_t)f * 128 + (uint32_t)q2 * 16) ^ (((uint32_t)(f & 7)) << 4);
            CP16(stg + O_HHI + sw, g_hT_hi + src);
            CP16(stg + O_HLO + sw, g_hT_lo + src);
        }
        CP_COMMIT();
    }

    // P tiles: warp w rows w*8..+7; thread: 2 rows x 8 j; B/Bp from smem
    int rbase = w * 8 + (lane >> 3) * 2;
    int jg = lane & 7;
    float4 Bv0 = *(const float4*)(sB  + jc + jg * 8);
    float4 Bv1 = *(const float4*)(sB  + jc + jg * 8 + 4);
    float4 Bp0 = *(const float4*)(sBp + jc + jg * 8);
    float4 Bp1 = *(const float4*)(sBp + jc + jg * 8 + 4);
    #pragma unroll
    for (int rr = 0; rr < 2; ++rr) {
        int R = rbase + rr;
        const int4* ap = (const int4*)(adj + (size_t)(i0 + R) * N_ + jc + jg * 8);
        int4 a0 = __ldcs(ap);
        int4 a1 = __ldcs(ap + 1);
        float Ar = sA[R], Apr = sAp[R];
        float p0 = (a0.x > 0) ? fmaxf(Ar * Bv0.x, Apr * Bp0.x) : 0.f;
        float p1 = (a0.y > 0) ? fmaxf(Ar * Bv0.y, Apr * Bp0.y) : 0.f;
        float p2 = (a0.z > 0) ? fmaxf(Ar * Bv0.z, Apr * Bp0.z) : 0.f;
        float p3 = (a0.w > 0) ? fmaxf(Ar * Bv0.w, Apr * Bp0.w) : 0.f;
        float p4 = (a1.x > 0) ? fmaxf(Ar * Bv1.x, Apr * Bp1.x) : 0.f;
        float p5 = (a1.y > 0) ? fmaxf(Ar * Bv1.y, Apr * Bp1.y) : 0.f;
        float p6 = (a1.z > 0) ? fmaxf(Ar * Bv1.z, Apr * Bp1.z) : 0.f;
        float p7 = (a1.w > 0) ? fmaxf(Ar * Bv1.w, Apr * Bp1.w) : 0.f;
        lp[rr] += ((p0 + p1) + (p2 + p3)) + ((p4 + p5) + (p6 + p7));

        uint32_t u0 = __float_as_uint(p0), u1 = __float_as_uint(p1);
        uint32_t u2 = __float_as_uint(p2), u3 = __float_as_uint(p3);
        uint32_t u4 = __float_as_uint(p4), u5 = __float_as_uint(p5);
        uint32_t u6 = __float_as_uint(p6), u7 = __float_as_uint(p7);
        uint32_t h01 = prmt_hi(u0, u1), h23 = prmt_hi(u2, u3);
        uint32_t h45 = prmt_hi(u4, u5), h67 = prmt_hi(u6, u7);
        float lo0 = p0 - __uint_as_float(u0 & 0xFFFF0000u);
        float lo1 = p1 - __uint_as_float(u1 & 0xFFFF0000u);
        float lo2 = p2 - __uint_as_float(u2 & 0xFFFF0000u);
        float lo3 = p3 - __uint_as_float(u3 & 0xFFFF0000u);
        float lo4 = p4 - __uint_as_float(u4 & 0xFFFF0000u);
        float lo5 = p5 - __uint_as_float(u5 & 0xFFFF0000u);
        float lo6 = p6 - __uint_as_float(u6 & 0xFFFF0000u);
        float lo7 = p7 - __uint_as_float(u7 & 0xFFFF0000u);
        __nv_bfloat162 l01 = __float22bfloat162_rn(make_float2(lo0, lo1));
        __nv_bfloat162 l23 = __float22bfloat162_rn(make_float2(lo2, lo3));
        __nv_bfloat162 l45 = __float22bfloat162_rn(make_float2(lo4, lo5));
        __nv_bfloat162 l67 = __float22bfloat162_rn(make_float2(lo6, lo7));

        uint32_t boff = (uint32_t)R * 128 + (uint32_t)jg * 16;
        uint32_t sw = boff ^ (((uint32_t)(R & 7)) << 4);
        *(uint4*)(stgp + O_PHI + sw) = make_uint4(h01, h23, h45, h67);
        *(uint4*)(stgp + O_PLO + sw) =
            make_uint4(*(uint32_t*)&l01, *(uint32_t*)&l23, *(uint32_t*)&l45, *(uint32_t*)&l67);
    }
    CP_WAIT0();   // my H copies landed before FULL arrive
}

__global__ void __launch_bounds__(384, 2) attn_kernel(
    const int* __restrict__ adj, float* __restrict__ out)
{
    extern __shared__ __align__(128) char sm[];
    uint32_t sb = smem_u32(sm);

    int t = threadIdx.x, w = t >> 5, lane = t & 31;
    int i0 = blockIdx.x * TI;
    int b = i0 >> 11;

    float* sA  = (float*)(sm + OFF_A);
    float* sAp = (float*)(sm + OFF_AP);
    float* sL  = (float*)(sm + OFF_L);
    float* sB  = (float*)(sm + OFF_B);
    float* sBp = (float*)(sm + OFF_BP);
    if (t < 64) { sA[t] = g_A[i0 + t]; sAp[t] = g_Ap[i0 + t]; }
    #pragma unroll
    for (int k = 0; k < 6; ++k) {   // 2048 floats each, 384 threads
        int u = t + k * 384;
        if (u < N_) {
            sB [u] = g_B [b * N_ + u];
            sBp[u] = g_Bp[b * N_ + u];
        }
    }
    __syncthreads();

    if (w < 8) {
        // ---------------- producers ----------------
        float lp[2] = {0.f, 0.f};
        for (int c = 0; c < NCH; ++c) {
            if (c >= 3) BAR_SYNC(4 + (c % 3));         // stage free?
            produce_chunk(sm, sb, adj, i0, b, c, t, w, lane, sA, sAp, sB, sBp, lp);
            BAR_ARRIVE(1 + (c % 3));                   // stage full
        }
        // denominators: reduce over 8 j-lanes, publish to sL
        int rbase = w * 8 + (lane >> 3) * 2;
        #pragma unroll
        for (int rr = 0; rr < 2; ++rr) {
            float v = lp[rr];
            v += __shfl_xor_sync(0xffffffffu, v, 1);
            v += __shfl_xor_sync(0xffffffffu, v, 2);
            v += __shfl_xor_sync(0xffffffffu, v, 4);
            if ((lane & 7) == 0) {
                sL[rbase + rr] = v;
                if (!(v >= 1e-20f)) {
                    int si = atomicAdd(&g_nbad, 1);
                    g_bad[si] = i0 + rbase + rr;
                }
            }
        }
        BAR_ARRIVE(7);                                 // denominators ready
    } else {
        // ---------------- consumers (4 warps, m32 x f32) ----------------
        float C[2][4][4];
        #pragma unroll
        for (int mt = 0; mt < 2; ++mt)
            #pragma unroll
            for (int g = 0; g < 4; ++g)
                #pragma unroll
                for (int qq = 0; qq < 4; ++qq) C[mt][g][qq] = 0.f;

        int cw = w - 8;
        int m0 = (cw & 1) * 32;
        int f0 = (cw >> 1) * 32;

        for (int c = 0; c < NCH; ++c) {
            BAR_SYNC(1 + (c % 3));                     // stage full?
            uint32_t stg = sb + (uint32_t)(c % 3) * STG;
            #pragma unroll
            for (int ks = 0; ks < 4; ++ks) {
                uint32_t ahi[2][4], alo[2][4];
                #pragma unroll
                for (int mt = 0; mt < 2; ++mt) {
                    int arow = m0 + mt * 16 + (lane & 15);
                    uint32_t aoff = (uint32_t)arow * 128 + (uint32_t)ks * 32 + ((uint32_t)(lane >> 4)) * 16;
                    uint32_t asw = aoff ^ (((uint32_t)(arow & 7)) << 4);
                    LDSM4(ahi[mt], stg + O_PHI + asw);
                    LDSM4(alo[mt], stg + O_PLO + asw);
                }
                #pragma unroll
                for (int nb = 0; nb < 2; ++nb) {
                    uint32_t bhi[4], blo[4];
                    int nrow = f0 + nb * 16 + (lane & 15);
                    uint32_t boff = (uint32_t)nrow * 128 + (uint32_t)ks * 32 + ((uint32_t)(lane >> 4)) * 16;
                    uint32_t bsw = boff ^ (((uint32_t)(nrow & 7)) << 4);
                    LDSM4(bhi, stg + O_HHI + bsw);
                    LDSM4(blo, stg + O_HLO + bsw);
                    #pragma unroll
                    for (int mt = 0; mt < 2; ++mt) {
                        MMA_BF16(C[mt][nb * 2],     ahi[mt], bhi[0], bhi[2]);
                        MMA_BF16(C[mt][nb * 2 + 1], ahi[mt], bhi[1], bhi[3]);
                        MMA_BF16(C[mt][nb * 2],     ahi[mt], blo[0], blo[2]);
                        MMA_BF16(C[mt][nb * 2 + 1], ahi[mt], blo[1], blo[3]);
                        MMA_BF16(C[mt][nb * 2],     alo[mt], bhi[0], bhi[2]);
                        MMA_BF16(C[mt][nb * 2 + 1], alo[mt], bhi[1], bhi[3]);
                    }
                }
            }
            BAR_ARRIVE(4 + (c % 3));                   // stage empty
        }

        BAR_SYNC(7);                                   // denominators ready

        // epilogue: normalize, ELU, write out directly
        int fo = f0 + (lane & 3) * 2;
        #pragma unroll
        for (int mt = 0; mt < 2; ++mt) {
            int lr0 = m0 + mt * 16 + (lane >> 2);
            float inv0 = 1.f / sL[lr0];
            float inv1 = 1.f / sL[lr0 + 8];
            float* o0 = out + (size_t)(i0 + lr0) * F_ + fo;
            float* o1 = o0 + 8 * F_;
            #pragma unroll
            for (int g = 0; g < 4; ++g) {
                float a0 = C[mt][g][0] * inv0, a1 = C[mt][g][1] * inv0;
                float b0 = C[mt][g][2] * inv1, b1 = C[mt][g][3] * inv1;
                a0 = (a0 > 0.f) ? a0 : (__expf(a0) - 1.f);
                a1 = (a1 > 0.f) ? a1 : (__expf(a1) - 1.f);
                b0 = (b0 > 0.f) ? b0 : (__expf(b0) - 1.f);
                b1 = (b1 > 0.f) ? b1 : (__expf(b1) - 1.f);
                *(float2*)(o0 + g * 8) = make_float2(a0, a1);
                *(float2*)(o1 + g * 8) = make_float2(b0, b1);
            }
        }
    }
}

// ---------------------------------------------------------------------------
// K4: exact fp32 recompute of flagged rows
// ---------------------------------------------------------------------------
__global__ void __launch_bounds__(256) fallback_kernel(
    const int* __restrict__ adj, float* __restrict__ out)
{
    __shared__ float p_s[N_];
    __shared__ float red[4][64];
    __shared__ float lred[8];
    int t = threadIdx.x, w = t >> 5, lane = t & 31;
    int nb = g_nbad;
    for (int k = blockIdx.x; k < nb; k += gridDim.x) {
        int row = g_bad[k];
        int b = row >> 11;
        float A = g_A[row], Ap = g_Ap[row];
        float lpv = 0.f;
        for (int j = t; j < N_; j += 256) {
            int av = adj[(size_t)row * N_ + j];
            float p = (av > 0) ? fmaxf(A * g_B[b * N_ + j], Ap * g_Bp[b * N_ + j]) : 0.f;
            p_s[j] = p;
            lpv += p;
        }
        #pragma unroll
        for (int off = 16; off; off >>= 1) lpv += __shfl_xor_sync(0xffffffffu, lpv, off);
        if (lane == 0) lred[w] = lpv;
        __syncthreads();
        float l = 0.f;
        #pragma unroll
        for (int q = 0; q < 8; ++q) l += lred[q];
        int f = t & 63, seg = t >> 6;
        float acc = 0.f;
        const float* hb = g_h + ((size_t)b * N_ + seg * 512) * F_ + f;
        for (int j = 0; j < 512; ++j) acc = fmaf(p_s[seg * 512 + j], hb[(size_t)j * F_], acc);
        red[seg][f] = acc;
        __syncthreads();
        if (t < 64) {
            float v = (red[0][t] + red[1][t] + red[2][t] + red[3][t]) / l;
            out[(size_t)row * F_ + t] = (v > 0.f) ? v : (__expf(v) - 1.f);
        }
        __syncthreads();
    }
}

extern "C" void kernel_launch(void* const* d_in, const int* in_sizes, int n_in,
                              void* d_out, int out_size)
{
    const float* x   = (const float*)d_in[0];
    const int*   adj = (const int*)  d_in[1];
    const float* W   = (const float*)d_in[2];
    const float* a   = (const float*)d_in[3];
    float* out = (float*)d_out;

    cudaFuncSetAttribute(attn_kernel, cudaFuncAttributeMaxDynamicSharedMemorySize, DSMEM);

    prep_kernel<<<(B_ * N_) / 16, 1024>>>(x, W, a);
    factors_kernel<<<(B_ * N_) / 256, 256>>>();
    reset_kernel<<<1, 32>>>();
    attn_kernel<<<B_ * N_ / TI, 384, DSMEM>>>(adj, out);
    fallback_kernel<<<32, 256>>>(adj, out);
}

// round 17
// speedup vs baseline: 1.2142x; 1.0516x over previous
#include <cuda_runtime.h>
#include <cuda_bf16.h>
#include <cstdint>

static constexpr int B_ = 8;
static constexpr int N_ = 2048;
static constexpr int F_ = 64;
static constexpr float ALPHA_ = 0.2f;
static constexpr int NCH = N_ / 64;      // 32 chunks, full j-range per block
static constexpr int TI = 64;            // rows per block

// -------- scratch (no cudaMalloc allowed) --------
__device__ float g_h[B_ * N_ * F_];
__device__ float g_s1[B_ * N_];
__device__ float g_s2[B_ * N_];
__device__ float g_c[B_];
__device__ float g_c2[B_];
__device__ float g_A [B_ * N_];
__device__ float g_Ap[B_ * N_];
__device__ float g_B [B_ * N_];
__device__ float g_Bp[B_ * N_];
__device__ __nv_bfloat16 g_hT_hi[B_ * F_ * N_];   // [b][f][n]
__device__ __nv_bfloat16 g_hT_lo[B_ * F_ * N_];
__device__ int g_nbad;
__device__ int g_bad[B_ * N_];

__device__ __forceinline__ uint32_t smem_u32(const void* p) {
    uint32_t a;
    asm("{ .reg .u64 t; cvta.to.shared.u64 t, %1; cvt.u32.u64 %0, t; }" : "=r"(a) : "l"(p));
    return a;
}

#define LDSM4(r, addr) \
    asm volatile("ldmatrix.sync.aligned.m8n8.x4.shared.b16 {%0,%1,%2,%3}, [%4];" \
        : "=r"((r)[0]), "=r"((r)[1]), "=r"((r)[2]), "=r"((r)[3]) : "r"(addr))

#define MMA_BF16(C, a, b0, b1) \
    asm volatile("mma.sync.aligned.m16n8k16.row.col.f32.bf16.bf16.f32 " \
        "{%0,%1,%2,%3}, {%4,%5,%6,%7}, {%8,%9}, {%0,%1,%2,%3};" \
        : "+f"((C)[0]), "+f"((C)[1]), "+f"((C)[2]), "+f"((C)[3]) \
        : "r"((a)[0]), "r"((a)[1]), "r"((a)[2]), "r"((a)[3]), "r"(b0), "r"(b1))

#define CP16(dst, src) \
    asm volatile("cp.async.cg.shared.global [%0], [%1], 16;" :: "r"(dst), "l"(src))
#define CP_COMMIT() asm volatile("cp.async.commit_group;" ::: "memory")
#define CP_WAIT0()  asm volatile("cp.async.wait_group 0;" ::: "memory")

#define PREFETCH_L2(p) asm volatile("prefetch.global.L2 [%0];" :: "l"(p))

// named block barriers (384 participants: 256 producer + 128 consumer threads)
#define BAR_SYNC(id)   asm volatile("bar.sync %0, 384;"   :: "r"(id) : "memory")
#define BAR_ARRIVE(id) asm volatile("bar.arrive %0, 384;" :: "r"(id) : "memory")

// ---------------------------------------------------------------------------
// K1: h = x@W ; s1,s2 ; transposed bf16 hi/lo copies of h
// ---------------------------------------------------------------------------
__global__ void __launch_bounds__(1024) prep_kernel(
    const float* __restrict__ x, const float* __restrict__ W, const float* __restrict__ a)
{
    __shared__ float W_s[F_ * F_];
    __shared__ float x_s[16][F_];
    __shared__ float h_sh[16][F_ + 1];
    __shared__ float red[16][2][2];

    int t = threadIdx.x, tx = t & 63, ty = t >> 6;
    int row0 = blockIdx.x * 16;
    int row = row0 + ty;

    #pragma unroll
    for (int k = 0; k < 4; ++k) W_s[t + k * 1024] = W[t + k * 1024];
    x_s[ty][tx] = x[(size_t)row * F_ + tx];
    __syncthreads();

    float h = 0.f;
    #pragma unroll
    for (int k = 0; k < F_; ++k) h = fmaf(x_s[ty][k], W_s[k * F_ + tx], h);
    g_h[(size_t)row * F_ + tx] = h;
    h_sh[ty][tx] = h;

    float v1 = h * a[tx];
    float v2 = h * a[F_ + tx];
    #pragma unroll
    for (int off = 16; off; off >>= 1) {
        v1 += __shfl_xor_sync(0xffffffffu, v1, off);
        v2 += __shfl_xor_sync(0xffffffffu, v2, off);
    }
    if ((tx & 31) == 0) { red[ty][tx >> 5][0] = v1; red[ty][tx >> 5][1] = v2; }
    __syncthreads();
    if (tx == 0) {
        g_s1[row] = red[ty][0][0] + red[ty][1][0];
        g_s2[row] = red[ty][0][1] + red[ty][1][1];
    }

    int f = t >> 4, rr = t & 15;
    float v = h_sh[rr][f];
    __nv_bfloat16 hi = __float2bfloat16(v);
    float lov = v - __bfloat162float(hi);
    int b = row0 >> 11;
    size_t o = ((size_t)(b * F_ + f)) * N_ + (row0 & (N_ - 1)) + rr;
    g_hT_hi[o] = hi;
    g_hT_lo[o] = __float2bfloat16(lov);
}

// ---------------------------------------------------------------------------
// K2: per-batch c (max of warp maxes) / c2 (min of warp maxes); reset counter
// ---------------------------------------------------------------------------
__global__ void __launch_bounds__(256) cmax_kernel() {
    __shared__ float red[8];
    int b = blockIdx.x, t = threadIdx.x, w = t >> 5, lane = t & 31;
    if (b == 0 && t == 0) g_nbad = 0;

    float m = -3.4e38f;
    for (int i = t; i < N_; i += 256) m = fmaxf(m, g_s2[b * N_ + i]);
    #pragma unroll
    for (int off = 16; off; off >>= 1) m = fmaxf(m, __shfl_xor_sync(0xffffffffu, m, off));
    if (lane == 0) red[w] = m;
    __syncthreads();
    if (t == 0) {
        float c = -3.4e38f, c2 = 3.4e38f;
        #pragma unroll
        for (int q = 0; q < 8; ++q) { c = fmaxf(c, red[q]); c2 = fminf(c2, red[q]); }
        g_c[b] = c;
        g_c2[b] = c2;
    }
}

// K2b: factor arrays, full-GPU spread (64 blocks, 1 elt/thread)
__global__ void __launch_bounds__(256) factors_kernel() {
    int i = blockIdx.x * 256 + threadIdx.x;
    int b = i >> 11;
    float c = g_c[b], c2 = g_c2[b];
    float s1 = g_s1[i];
    float u  = s1 + c;
    float u2 = s1 + c2;
    float lr_u  = (u  > 0.f) ? u  : ALPHA_ * u;
    float lr_u2 = (u2 > 0.f) ? u2 : ALPHA_ * u2;
    float mm = fmaxf(lr_u2, lr_u - 60.f);
    g_A [i] = expf(u - mm);
    g_Ap[i] = expf(ALPHA_ * u - mm);
    float v = g_s2[i] - c;
    g_B [i] = expf(v);
    g_Bp[i] = expf(ALPHA_ * v);
}

// ---------------------------------------------------------------------------
// K3: attention via HMMA, warp-specialized, 3-stage named-barrier pipeline.
// 256 blocks x 384 thr: warps 0-7 producers (H cp.async + adj __ldcs -> P
// truncation-split -> smem + denominators + L2 prefetch of next adj chunk),
// warps 8-11 consumers (LDSM + MMA m32 x f32 + direct epilogue).
// ---------------------------------------------------------------------------
static constexpr uint32_t STG    = 32768;   // Phi 8K | Plo 8K | Hhi 8K | Hlo 8K
static constexpr uint32_t O_PHI  = 0;
static constexpr uint32_t O_PLO  = 8192;
static constexpr uint32_t O_HHI  = 16384;
static constexpr uint32_t O_HLO  = 24576;
static constexpr uint32_t OFF_A  = 98304;   // 256B (64 floats)
static constexpr uint32_t OFF_AP = 98560;   // 256B
static constexpr uint32_t OFF_L  = 98816;   // 256B
static constexpr uint32_t DSMEM  = 99072;

// truncation split: hi = trunc-bf16(p) (p >= 0), lo = p - hi exact, RN on lo
__device__ __forceinline__ uint32_t prmt_hi(uint32_t u0, uint32_t u1) {
    uint32_t r;
    asm("prmt.b32 %0, %1, %2, 0x7632;" : "=r"(r) : "r"(u0), "r"(u1));
    return r;
}

// Producer: stage H(cidx) via cp.async + produce P(cidx) into stage[cidx%3].
// Also L2-prefetches adj for chunk cidx+1. Called only by threads t < 256.
__device__ __forceinline__ void produce_chunk(
    char* sm, uint32_t sb, const int* __restrict__ adj,
    int i0, int b, int cidx, int t, int w, int lane,
    const float* sA, const float* sAp, float* lp)
{
    int st = cidx % 3;
    uint32_t stg = sb + (uint32_t)st * STG;
    char*   stgp = sm + (uint32_t)st * STG;
    int jc = cidx * 64;

    // H tiles: 64 f-rows x 64 j bf16 hi/lo, swizzled, via cp.async
    {
        int f = t >> 2;
        int q0 = (t & 3) * 2;
        #pragma unroll
        for (int hp = 0; hp < 2; ++hp) {
            int q2 = q0 + hp;
            size_t src = ((size_t)(b * F_ + f)) * N_ + jc + q2 * 8;
            uint32_t sw = ((uint32_t)f * 128 + (uint32_t)q2 * 16) ^ (((uint32_t)(f & 7)) << 4);
            CP16(stg + O_HHI + sw, g_hT_hi + src);
            CP16(stg + O_HLO + sw, g_hT_lo + src);
        }
        CP_COMMIT();
    }

    // P tiles: warp w rows w*8..+7; thread: 2 rows x 8 j
    int rbase = w * 8 + (lane >> 3) * 2;
    int jg = lane & 7;
    const float4* Bg  = (const float4*)(g_B  + b * N_ + jc + jg * 8);
    const float4* Bpg = (const float4*)(g_Bp + b * N_ + jc + jg * 8);
    float4 Bv0 = __ldg(Bg);
    float4 Bv1 = __ldg(Bg + 1);
    float4 Bp0 = __ldg(Bpg);
    float4 Bp1 = __ldg(Bpg + 1);
    #pragma unroll
    for (int rr = 0; rr < 2; ++rr) {
        int R = rbase + rr;
        const int4* ap = (const int4*)(adj + (size_t)(i0 + R) * N_ + jc + jg * 8);
        int4 a0 = __ldcs(ap);
        int4 a1 = __ldcs(ap + 1);
        float Ar = sA[R], Apr = sAp[R];
        float p0 = (a0.x > 0) ? fmaxf(Ar * Bv0.x, Apr * Bp0.x) : 0.f;
        float p1 = (a0.y > 0) ? fmaxf(Ar * Bv0.y, Apr * Bp0.y) : 0.f;
        float p2 = (a0.z > 0) ? fmaxf(Ar * Bv0.z, Apr * Bp0.z) : 0.f;
        float p3 = (a0.w > 0) ? fmaxf(Ar * Bv0.w, Apr * Bp0.w) : 0.f;
        float p4 = (a1.x > 0) ? fmaxf(Ar * Bv1.x, Apr * Bp1.x) : 0.f;
        float p5 = (a1.y > 0) ? fmaxf(Ar * Bv1.y, Apr * Bp1.y) : 0.f;
        float p6 = (a1.z > 0) ? fmaxf(Ar * Bv1.z, Apr * Bp1.z) : 0.f;
        float p7 = (a1.w > 0) ? fmaxf(Ar * Bv1.w, Apr * Bp1.w) : 0.f;
        lp[rr] += ((p0 + p1) + (p2 + p3)) + ((p4 + p5) + (p6 + p7));

        uint32_t u0 = __float_as_uint(p0), u1 = __float_as_uint(p1);
        uint32_t u2 = __float_as_uint(p2), u3 = __float_as_uint(p3);
        uint32_t u4 = __float_as_uint(p4), u5 = __float_as_uint(p5);
        uint32_t u6 = __float_as_uint(p6), u7 = __float_as_uint(p7);
        uint32_t h01 = prmt_hi(u0, u1), h23 = prmt_hi(u2, u3);
        uint32_t h45 = prmt_hi(u4, u5), h67 = prmt_hi(u6, u7);
        float lo0 = p0 - __uint_as_float(u0 & 0xFFFF0000u);
        float lo1 = p1 - __uint_as_float(u1 & 0xFFFF0000u);
        float lo2 = p2 - __uint_as_float(u2 & 0xFFFF0000u);
        float lo3 = p3 - __uint_as_float(u3 & 0xFFFF0000u);
        float lo4 = p4 - __uint_as_float(u4 & 0xFFFF0000u);
        float lo5 = p5 - __uint_as_float(u5 & 0xFFFF0000u);
        float lo6 = p6 - __uint_as_float(u6 & 0xFFFF0000u);
        float lo7 = p7 - __uint_as_float(u7 & 0xFFFF0000u);
        __nv_bfloat162 l01 = __float22bfloat162_rn(make_float2(lo0, lo1));
        __nv_bfloat162 l23 = __float22bfloat162_rn(make_float2(lo2, lo3));
        __nv_bfloat162 l45 = __float22bfloat162_rn(make_float2(lo4, lo5));
        __nv_bfloat162 l67 = __float22bfloat162_rn(make_float2(lo6, lo7));

        uint32_t boff = (uint32_t)R * 128 + (uint32_t)jg * 16;
        uint32_t sw = boff ^ (((uint32_t)(R & 7)) << 4);
        *(uint4*)(stgp + O_PHI + sw) = make_uint4(h01, h23, h45, h67);
        *(uint4*)(stgp + O_PLO + sw) =
            make_uint4(*(uint32_t*)&l01, *(uint32_t*)&l23, *(uint32_t*)&l45, *(uint32_t*)&l67);
    }

    // L2-prefetch next chunk's adj (no registers, no smem, keeps coalescing)
    {
        int jn = jc + ((cidx + 1 < NCH) ? 64 : 0);
        #pragma unroll
        for (int rr = 0; rr < 2; ++rr) {
            const int4* ap = (const int4*)(adj + (size_t)(i0 + rbase + rr) * N_ + jn + jg * 8);
            PREFETCH_L2(ap);
            PREFETCH_L2(ap + 1);
        }
    }

    CP_WAIT0();   // my H copies landed before FULL arrive
}

__global__ void __launch_bounds__(384, 2) attn_kernel(
    const int* __restrict__ adj, float* __restrict__ out)
{
    extern __shared__ __align__(128) char sm[];
    uint32_t sb = smem_u32(sm);

    int t = threadIdx.x, w = t >> 5, lane = t & 31;
    int i0 = blockIdx.x * TI;
    int b = i0 >> 11;

    float* sA  = (float*)(sm + OFF_A);
    float* sAp = (float*)(sm + OFF_AP);
    float* sL  = (float*)(sm + OFF_L);
    if (t < 64) { sA[t] = g_A[i0 + t]; sAp[t] = g_Ap[i0 + t]; }
    __syncthreads();

    if (w < 8) {
        // ---------------- producers ----------------
        float lp[2] = {0.f, 0.f};
        for (int c = 0; c < NCH; ++c) {
            if (c >= 3) BAR_SYNC(4 + (c % 3));         // stage free?
            produce_chunk(sm, sb, adj, i0, b, c, t, w, lane, sA, sAp, lp);
            BAR_ARRIVE(1 + (c % 3));                   // stage full
        }
        // denominators: reduce over 8 j-lanes, publish to sL
        int rbase = w * 8 + (lane >> 3) * 2;
        #pragma unroll
        for (int rr = 0; rr < 2; ++rr) {
            float v = lp[rr];
            v += __shfl_xor_sync(0xffffffffu, v, 1);
            v += __shfl_xor_sync(0xffffffffu, v, 2);
            v += __shfl_xor_sync(0xffffffffu, v, 4);
            if ((lane & 7) == 0) {
                sL[rbase + rr] = v;
                if (!(v >= 1e-20f)) {
                    int si = atomicAdd(&g_nbad, 1);
                    g_bad[si] = i0 + rbase + rr;
                }
            }
        }
        BAR_ARRIVE(7);                                 // denominators ready
    } else {
        // ---------------- consumers (4 warps, m32 x f32) ----------------
        float C[2][4][4];
        #pragma unroll
        for (int mt = 0; mt < 2; ++mt)
            #pragma unroll
            for (int g = 0; g < 4; ++g)
                #pragma unroll
                for (int qq = 0; qq < 4; ++qq) C[mt][g][qq] = 0.f;

        int cw = w - 8;
        int m0 = (cw & 1) * 32;
        int f0 = (cw >> 1) * 32;

        for (int c = 0; c < NCH; ++c) {
            BAR_SYNC(1 + (c % 3));                     // stage full?
            uint32_t stg = sb + (uint32_t)(c % 3) * STG;
            #pragma unroll
            for (int ks = 0; ks < 4; ++ks) {
                uint32_t ahi[2][4], alo[2][4];
                #pragma unroll
                for (int mt = 0; mt < 2; ++mt) {
                    int arow = m0 + mt * 16 + (lane & 15);
                    uint32_t aoff = (uint32_t)arow * 128 + (uint32_t)ks * 32 + ((uint32_t)(lane >> 4)) * 16;
                    uint32_t asw = aoff ^ (((uint32_t)(arow & 7)) << 4);
                    LDSM4(ahi[mt], stg + O_PHI + asw);
                    LDSM4(alo[mt], stg + O_PLO + asw);
                }
                #pragma unroll
                for (int nb = 0; nb < 2; ++nb) {
                    uint32_t bhi[4], blo[4];
                    int nrow = f0 + nb * 16 + (lane & 15);
                    uint32_t boff = (uint32_t)nrow * 128 + (uint32_t)ks * 32 + ((uint32_t)(lane >> 4)) * 16;
                    uint32_t bsw = boff ^ (((uint32_t)(nrow & 7)) << 4);
                    LDSM4(bhi, stg + O_HHI + bsw);
                    LDSM4(blo, stg + O_HLO + bsw);
                    #pragma unroll
                    for (int mt = 0; mt < 2; ++mt) {
                        MMA_BF16(C[mt][nb * 2],     ahi[mt], bhi[0], bhi[2]);
                        MMA_BF16(C[mt][nb * 2 + 1], ahi[mt], bhi[1], bhi[3]);
                        MMA_BF16(C[mt][nb * 2],     ahi[mt], blo[0], blo[2]);
                        MMA_BF16(C[mt][nb * 2 + 1], ahi[mt], blo[1], blo[3]);
                        MMA_BF16(C[mt][nb * 2],     alo[mt], bhi[0], bhi[2]);
                        MMA_BF16(C[mt][nb * 2 + 1], alo[mt], bhi[1], bhi[3]);
                    }
                }
            }
            BAR_ARRIVE(4 + (c % 3));                   // stage empty
        }

        BAR_SYNC(7);                                   // denominators ready

        // epilogue: normalize, ELU, write out directly
        int fo = f0 + (lane & 3) * 2;
        #pragma unroll
        for (int mt = 0; mt < 2; ++mt) {
            int lr0 = m0 + mt * 16 + (lane >> 2);
            float inv0 = 1.f / sL[lr0];
            float inv1 = 1.f / sL[lr0 + 8];
            float* o0 = out + (size_t)(i0 + lr0) * F_ + fo;
            float* o1 = o0 + 8 * F_;
            #pragma unroll
            for (int g = 0; g < 4; ++g) {
                float a0 = C[mt][g][0] * inv0, a1 = C[mt][g][1] * inv0;
                float b0 = C[mt][g][2] * inv1, b1 = C[mt][g][3] * inv1;
                a0 = (a0 > 0.f) ? a0 : (__expf(a0) - 1.f);
                a1 = (a1 > 0.f) ? a1 : (__expf(a1) - 1.f);
                b0 = (b0 > 0.f) ? b0 : (__expf(b0) - 1.f);
                b1 = (b1 > 0.f) ? b1 : (__expf(b1) - 1.f);
                *(float2*)(o0 + g * 8) = make_float2(a0, a1);
                *(float2*)(o1 + g * 8) = make_float2(b0, b1);
            }
        }
    }
}

// ---------------------------------------------------------------------------
// K4: exact fp32 recompute of flagged rows
// ---------------------------------------------------------------------------
__global__ void __launch_bounds__(256) fallback_kernel(
    const int* __restrict__ adj, float* __restrict__ out)
{
    __shared__ float p_s[N_];
    __shared__ float red[4][64];
    __shared__ float lred[8];
    int t = threadIdx.x, w = t >> 5, lane = t & 31;
    int nb = g_nbad;
    for (int k = blockIdx.x; k < nb; k += gridDim.x) {
        int row = g_bad[k];
        int b = row >> 11;
        float A = g_A[row], Ap = g_Ap[row];
        float lpv = 0.f;
        for (int j = t; j < N_; j += 256) {
            int av = adj[(size_t)row * N_ + j];
            float p = (av > 0) ? fmaxf(A * g_B[b * N_ + j], Ap * g_Bp[b * N_ + j]) : 0.f;
            p_s[j] = p;
            lpv += p;
        }
        #pragma unroll
        for (int off = 16; off; off >>= 1) lpv += __shfl_xor_sync(0xffffffffu, lpv, off);
        if (lane == 0) lred[w] = lpv;
        __syncthreads();
        float l = 0.f;
        #pragma unroll
        for (int q = 0; q < 8; ++q) l += lred[q];
        int f = t & 63, seg = t >> 6;
        float acc = 0.f;
        const float* hb = g_h + ((size_t)b * N_ + seg * 512) * F_ + f;
        for (int j = 0; j < 512; ++j) acc = fmaf(p_s[seg * 512 + j], hb[(size_t)j * F_], acc);
        red[seg][f] = acc;
        __syncthreads();
        if (t < 64) {
            float v = (red[0][t] + red[1][t] + red[2][t] + red[3][t]) / l;
            out[(size_t)row * F_ + t] = (v > 0.f) ? v : (__expf(v) - 1.f);
        }
        __syncthreads();
    }
}

extern "C" void kernel_launch(void* const* d_in, const int* in_sizes, int n_in,
                              void* d_out, int out_size)
{
    const float* x   = (const float*)d_in[0];
    const int*   adj = (const int*)  d_in[1];
    const float* W   = (const float*)d_in[2];
    const float* a   = (const float*)d_in[3];
    float* out = (float*)d_out;

    cudaFuncSetAttribute(attn_kernel, cudaFuncAttributeMaxDynamicSharedMemorySize, DSMEM);

    prep_kernel<<<(B_ * N_) / 16, 1024>>>(x, W, a);
    cmax_kernel<<<B_, 256>>>();
    factors_kernel<<<(B_ * N_) / 256, 256>>>();
    attn_kernel<<<B_ * N_ / TI, 384, DSMEM>>>(adj, out);
    fallback_kernel<<<24, 256>>>(adj, out);
}